// round 12
// baseline (speedup 1.0000x reference)
#include <cuda_runtime.h>
#include <cstdint>
#include <math.h>

// Problem dims
#define T_SEQ 512
#define BATCH 8
#define HID   512
#define EMB   256
#define VOCAB 32000
#define M_TOT (BATCH*T_SEQ)   // 4096
#define G4H   (4*HID)         // 2048

typedef unsigned long long u64;

// ---------------- scratch (device globals; no allocation allowed) -----------
__device__ float    g_x0 [M_TOT*EMB];      // gathered embeddings
__device__ float    g_xg [M_TOT*G4H];      // layer0 input-gate contributions
__device__ float    g_hs1[M_TOT*HID];      // layer1 outputs (FC input)
__device__ float    g_h0 [2][HID*BATCH];   // double-buffered h0, layout [n][b]
__device__ float    g_h1 [2][HID*BATCH];   // double-buffered h1
__device__ unsigned g_bar;                 // monotonic wavefront barrier
__device__ unsigned g_abort;               // safety abort flag

// ---------------- embedding gather ------------------------------------------
__global__ void gather_kernel(const int* __restrict__ ids,
                              const float* __restrict__ emb) {
    int m  = blockIdx.x;
    int id = ids[m];
    const float4* s = (const float4*)(emb + (size_t)id * EMB);
    float4*       d = (float4*)(g_x0 + (size_t)m * EMB);
    d[threadIdx.x] = s[threadIdx.x];
}

// ---------------- barrier / h-buffer reset (before the recurrence) ----------
__global__ void reset_kernel() {
    int i = blockIdx.x * blockDim.x + threadIdx.x;
    if (i == 0) { g_bar = 0u; g_abort = 0u; }
    if (i < HID * BATCH) {
        g_h0[0][i] = 0.f; g_h0[1][i] = 0.f;
        g_h1[0][i] = 0.f; g_h1[1][i] = 0.f;
    }
}

// ---------------- tf32 mma GEMM, double-buffered -----------------------------
// C[m][n] = sum_k A[m][k]*B[n][k] + bias.  A row-major [M][K], B row-major
// [N][K]; M%128==0, N%128==0, K%32==0.  Two smem tile buffers; K-tile t+1 is
// loaded into registers while mma consumes tile t; ONE syncthreads per K-iter.
__device__ __forceinline__ float f2tf32(float x) {
    float r;
    asm("cvt.rna.tf32.f32 %0, %1;" : "=f"(r) : "f"(x));
    return r;
}

#define TILE_F (128*36)          // floats per (As or Bs) buffer
#define GEMM_SMEM (4*TILE_F*4)   // bytes: 2 bufs x (As+Bs) = 73728

__global__ void __launch_bounds__(256)
gemm_tf32_kernel(const float* __restrict__ A, const float* __restrict__ B,
                 const float* __restrict__ bias1, const float* __restrict__ bias2,
                 float* __restrict__ C, int M, int N, int K)
{
    extern __shared__ float smg[];
    // buffers: As[b] = smg + b*TILE_F ; Bs[b] = smg + 2*TILE_F + b*TILE_F

    int tid  = threadIdx.x;
    int warp = tid >> 5, lane = tid & 31;
    int wm   = warp >> 2, wn = warp & 3;
    int grp  = lane >> 2, tig = lane & 3;

    int mBase = blockIdx.y << 7;
    int nBase = blockIdx.x << 7;

    // each thread stages 4 float4 of A and 4 of B per K-tile
    // slot f = tid + i*256 : row m = f>>3, k4 = (f&7)*4
    int srow[4], sk4[4];
    #pragma unroll
    for (int i = 0; i < 4; i++) {
        int f = tid + (i << 8);
        srow[i] = f >> 3;
        sk4[i]  = (f & 7) << 2;
    }

    float acc[4][4][4];
    #pragma unroll
    for (int a = 0; a < 4; a++)
        #pragma unroll
        for (int b = 0; b < 4; b++)
            #pragma unroll
            for (int c = 0; c < 4; c++) acc[a][b][c] = 0.f;

    int nkt = K >> 5;
    float4 ra[4], rb[4];

    // prefetch tile 0
    #pragma unroll
    for (int i = 0; i < 4; i++) {
        ra[i] = *(const float4*)(A + (size_t)(mBase + srow[i]) * K + sk4[i]);
        rb[i] = *(const float4*)(B + (size_t)(nBase + srow[i]) * K + sk4[i]);
    }

    for (int kt = 0; kt < nkt; kt++) {
        int cur = kt & 1;
        float* As = smg + cur * TILE_F;
        float* Bs = smg + 2 * TILE_F + cur * TILE_F;

        // store prefetched tile (convert to tf32 on the way)
        #pragma unroll
        for (int i = 0; i < 4; i++) {
            *(float4*)(As + srow[i] * 36 + sk4[i]) =
                make_float4(f2tf32(ra[i].x), f2tf32(ra[i].y),
                            f2tf32(ra[i].z), f2tf32(ra[i].w));
            *(float4*)(Bs + srow[i] * 36 + sk4[i]) =
                make_float4(f2tf32(rb[i].x), f2tf32(rb[i].y),
                            f2tf32(rb[i].z), f2tf32(rb[i].w));
        }
        __syncthreads();

        // prefetch next tile while mma consumes this one
        if (kt + 1 < nkt) {
            int k0 = (kt + 1) << 5;
            #pragma unroll
            for (int i = 0; i < 4; i++) {
                ra[i] = *(const float4*)(A + (size_t)(mBase + srow[i]) * K + k0 + sk4[i]);
                rb[i] = *(const float4*)(B + (size_t)(nBase + srow[i]) * K + k0 + sk4[i]);
            }
        }

        #pragma unroll
        for (int kk = 0; kk < 32; kk += 8) {
            uint32_t af[4][4], bf[4][2];
            #pragma unroll
            for (int mi = 0; mi < 4; mi++) {
                int r = (wm << 6) + (mi << 4);
                af[mi][0] = __float_as_uint(As[(r + grp    ) * 36 + kk + tig    ]);
                af[mi][1] = __float_as_uint(As[(r + grp + 8) * 36 + kk + tig    ]);
                af[mi][2] = __float_as_uint(As[(r + grp    ) * 36 + kk + tig + 4]);
                af[mi][3] = __float_as_uint(As[(r + grp + 8) * 36 + kk + tig + 4]);
            }
            #pragma unroll
            for (int ni = 0; ni < 4; ni++) {
                int cN = (wn << 5) + (ni << 3);
                bf[ni][0] = __float_as_uint(Bs[(cN + grp) * 36 + kk + tig    ]);
                bf[ni][1] = __float_as_uint(Bs[(cN + grp) * 36 + kk + tig + 4]);
            }
            #pragma unroll
            for (int mi = 0; mi < 4; mi++)
                #pragma unroll
                for (int ni = 0; ni < 4; ni++)
                    asm volatile(
                        "mma.sync.aligned.m16n8k8.row.col.f32.tf32.tf32.f32 "
                        "{%0,%1,%2,%3}, {%4,%5,%6,%7}, {%8,%9}, {%0,%1,%2,%3};"
                        : "+f"(acc[mi][ni][0]), "+f"(acc[mi][ni][1]),
                          "+f"(acc[mi][ni][2]), "+f"(acc[mi][ni][3])
                        : "r"(af[mi][0]), "r"(af[mi][1]),
                          "r"(af[mi][2]), "r"(af[mi][3]),
                          "r"(bf[ni][0]), "r"(bf[ni][1]));
        }
        // no second sync: next iteration writes the OTHER buffer, and its
        // syncthreads (after the store) orders everything.
    }

    #pragma unroll
    for (int mi = 0; mi < 4; mi++) {
        int mrow = mBase + (wm << 6) + (mi << 4) + grp;
        #pragma unroll
        for (int ni = 0; ni < 4; ni++) {
            int nc = nBase + (wn << 5) + (ni << 3) + (tig << 1);
            float b0 = __ldg(bias1 + nc), b1 = __ldg(bias1 + nc + 1);
            if (bias2) { b0 += __ldg(bias2 + nc); b1 += __ldg(bias2 + nc + 1); }
            float2 v0 = make_float2(acc[mi][ni][0] + b0, acc[mi][ni][1] + b1);
            float2 v1 = make_float2(acc[mi][ni][2] + b0, acc[mi][ni][3] + b1);
            *(float2*)(C + (size_t)mrow       * N + nc) = v0;
            *(float2*)(C + (size_t)(mrow + 8) * N + nc) = v1;
        }
    }
}

// ---------------- persistent wavefront LSTM (unchanged from R11, passing) ----
#define NCTA_TOT 128
#define WST0 516    // floats; row stride layer0 (512 + 4 pad)
#define WST1 1036   // floats; row stride layer1 concat [Whh1|Wih1] (1024 + 12)

#define FMA2(a, x, y) \
    asm("fma.rn.f32x2 %0, %1, %2, %0;" : "+l"(a) : "l"(x), "l"(y))

__global__ void __launch_bounds__(256)
lstm_persist_kernel(const float* __restrict__ Whh0, const float* __restrict__ xg,
                    const float* __restrict__ Whh1, const float* __restrict__ Wih1,
                    const float* __restrict__ bi1,  const float* __restrict__ bh1,
                    float* __restrict__ hs1)
{
    extern __shared__ float sm[];
    __shared__ int s_flag;
    int tid  = threadIdx.x;
    bool isL1 = blockIdx.x >= 64;
    int base = (isL1 ? blockIdx.x - 64 : blockIdx.x) << 3;   // first owned unit

    const int WST = isL1 ? WST1 : WST0;
    float* Ws = sm;                    // 32 rows x WST
    float* Hb = sm + 32 * WST;         //  8 x WST   (h inputs, [b][k])
    float* Pt = Hb + 8 * WST;          // 256 x 9 k-partials
    float* Gs = Pt + 256 * 9;          // 256 gate pre-activations
    float* Cs = Gs + 256;              // 64 cell states

    // ---- one-time staging: W slice (rows = g*8+u for owned units) ----
    if (!isL1) {
        #pragma unroll 4
        for (int i = tid; i < 4096; i += 256) {        // 32 rows x 128 float4
            int r = i >> 7, c4 = (i & 127) << 2;
            int g = r >> 3, u = r & 7;
            *(float4*)(Ws + r * WST0 + c4) =
                *(const float4*)(Whh0 + (size_t)((g << 9) + base + u) * HID + c4);
        }
    } else {
        #pragma unroll 4
        for (int i = tid; i < 8192; i += 256) {        // 32 rows x 256 float4
            int r = i >> 8, c4 = (i & 255) << 2;
            int g = r >> 3, u = r & 7;
            const float* src = (c4 < 512) ? Whh1 : Wih1;
            int col = (c4 < 512) ? c4 : c4 - 512;
            *(float4*)(Ws + r * WST1 + c4) =
                *(const float4*)(src + (size_t)((g << 9) + base + u) * HID + col);
        }
    }
    for (int i = tid; i < 8 * WST; i += 256) Hb[i] = 0.f;   // h_{-1} = 0
    if (tid < 64) Cs[tid] = 0.f;
    if (tid == 0) s_flag = 0;

    // reduce-phase constants: slot tid = (row, b); row = g*8+u
    int rrow = tid >> 3, rb = tid & 7;
    int rgrow = ((rrow >> 3) << 9) + base + (rrow & 7);     // global gate row
    float rbias = isL1 ? (__ldg(bi1 + rgrow) + __ldg(bh1 + rgrow)) : 0.f;
    __syncthreads();

    // dot-phase mapping: lane = row, warp = k slice
    int w    = tid >> 5, lane = tid & 31;
    int ncw  = isL1 ? 32 : 16;                 // 16B chunks per warp
    int cb   = w * ncw;                        // starting chunk
    const ulonglong2* wp = (const ulonglong2*)(Ws + lane * WST) + cb;

    unsigned* barp = &g_bar;
    volatile unsigned* abtp = (volatile unsigned*)&g_abort;

    for (int l = 0; l <= T_SEQ; l++) {
        int wpar   = l & 1;
        bool active = isL1 ? (l >= 1) : (l < T_SEQ);
        int t = isL1 ? (l - 1) : l;

        float xv = 0.f;
        if (!isL1 && active)               // issue early; hidden under the dot
            xv = __ldg(xg + (size_t)((rb << 9) + t) * G4H + rgrow);

        if (active) {
            u64 acc[8];
            #pragma unroll
            for (int b = 0; b < 8; b++) acc[b] = 0ull;

            const ulonglong2* h0p = (const ulonglong2*)(Hb + 0 * WST) + cb;
            const ulonglong2* h1p = (const ulonglong2*)(Hb + 1 * WST) + cb;
            const ulonglong2* h2p = (const ulonglong2*)(Hb + 2 * WST) + cb;
            const ulonglong2* h3p = (const ulonglong2*)(Hb + 3 * WST) + cb;
            const ulonglong2* h4p = (const ulonglong2*)(Hb + 4 * WST) + cb;
            const ulonglong2* h5p = (const ulonglong2*)(Hb + 5 * WST) + cb;
            const ulonglong2* h6p = (const ulonglong2*)(Hb + 6 * WST) + cb;
            const ulonglong2* h7p = (const ulonglong2*)(Hb + 7 * WST) + cb;

            #pragma unroll 4
            for (int c = 0; c < ncw; c++) {
                ulonglong2 wv = wp[c];
                ulonglong2 h;
                h = h0p[c]; FMA2(acc[0], wv.x, h.x); FMA2(acc[0], wv.y, h.y);
                h = h1p[c]; FMA2(acc[1], wv.x, h.x); FMA2(acc[1], wv.y, h.y);
                h = h2p[c]; FMA2(acc[2], wv.x, h.x); FMA2(acc[2], wv.y, h.y);
                h = h3p[c]; FMA2(acc[3], wv.x, h.x); FMA2(acc[3], wv.y, h.y);
                h = h4p[c]; FMA2(acc[4], wv.x, h.x); FMA2(acc[4], wv.y, h.y);
                h = h5p[c]; FMA2(acc[5], wv.x, h.x); FMA2(acc[5], wv.y, h.y);
                h = h6p[c]; FMA2(acc[6], wv.x, h.x); FMA2(acc[6], wv.y, h.y);
                h = h7p[c]; FMA2(acc[7], wv.x, h.x); FMA2(acc[7], wv.y, h.y);
            }
            #pragma unroll
            for (int b = 0; b < 8; b++) {
                float lo, hi;
                asm("mov.b64 {%0,%1}, %2;" : "=f"(lo), "=f"(hi) : "l"(acc[b]));
                Pt[((lane << 3) + b) * 9 + w] = lo + hi;
            }
        }
        __syncthreads();

        if (active) {                       // reduce k-partials, add bias/xg
            float s = 0.f;
            #pragma unroll
            for (int k = 0; k < 8; k++) s += Pt[tid * 9 + k];
            Gs[tid] = s + (isL1 ? rbias : xv);
        }
        __syncthreads();

        if (active && tid < 64) {           // activations + publish h
            int u = tid >> 3, b = tid & 7;
            int id = (u << 3) + b;
            float iv = Gs[id],       fv = Gs[64 + id];
            float gv = Gs[128 + id], ov = Gs[192 + id];
            float i_ = 1.f / (1.f + expf(-iv));
            float f_ = 1.f / (1.f + expf(-fv));
            float gg = tanhf(gv);
            float o_ = 1.f / (1.f + expf(-ov));
            float c  = f_ * Cs[id] + i_ * gg;
            Cs[id]   = c;
            float h  = o_ * tanhf(c);
            int n = base + u;
            if (!isL1) {
                g_h0[wpar][(n << 3) + b] = h;
            } else {
                g_h1[wpar][(n << 3) + b] = h;
                hs1[(size_t)((b << 9) + t) * HID + n] = h;
            }
        }
        __threadfence();                    // publish before signaling
        __syncthreads();

        if (tid == 0) {                     // bounded-spin wavefront barrier
            atomicAdd(barp, 1u);
            unsigned target = (unsigned)NCTA_TOT * (unsigned)(l + 1);
            int ab = 0;
            long it = 0;
            for (;;) {
                unsigned v;
                asm volatile("ld.volatile.global.u32 %0, [%1];"
                             : "=r"(v) : "l"(barp));
                if (v >= target) break;
                if (*abtp != 0u) { ab = 1; break; }
                if (++it > 4000000) { atomicExch(&g_abort, 1u); ab = 1; break; }
                __nanosleep(64);
            }
            s_flag = ab;
        }
        __syncthreads();
        if (s_flag) return;                 // hang-proof: give up, never spin forever
        __threadfence();                    // acquire

        // refresh Hb from the freshly written state (parity wpar)
        if (!isL1) {
            const float* src = g_h0[wpar];
            #pragma unroll 4
            for (int i = tid; i < HID * BATCH; i += 256) {
                int k = i >> 3, b = i & 7;
                Hb[b * WST0 + k] = __ldcg(src + i);
            }
        } else {
            const float* h1src = g_h1[wpar];
            const float* h0src = g_h0[wpar];
            #pragma unroll 4
            for (int i = tid; i < 2 * HID * BATCH; i += 256) {
                int half = i >> 12;         // 0: h1 -> cols [0,512), 1: h0 -> [512,1024)
                int j = i & 4095;
                int k = j >> 3, b = j & 7;
                Hb[b * WST1 + (half << 9) + k] =
                    __ldcg((half ? h0src : h1src) + j);
            }
        }
        __syncthreads();
    }
}

// ---------------- launch -----------------------------------------------------
extern "C" void kernel_launch(void* const* d_in, const int* in_sizes, int n_in,
                              void* d_out, int out_size)
{
    (void)in_sizes; (void)n_in; (void)out_size;
    const int*   ids   = (const int*)d_in[0];
    const float* emb   = (const float*)d_in[1];
    const float* W_ih0 = (const float*)d_in[2];
    const float* W_hh0 = (const float*)d_in[3];
    const float* b_ih0 = (const float*)d_in[4];
    const float* b_hh0 = (const float*)d_in[5];
    const float* W_ih1 = (const float*)d_in[6];
    const float* W_hh1 = (const float*)d_in[7];
    const float* b_ih1 = (const float*)d_in[8];
    const float* b_hh1 = (const float*)d_in[9];
    const float* W_fc  = (const float*)d_in[10];
    const float* b_fc  = (const float*)d_in[11];
    float* out = (float*)d_out;

    float *x0, *xgp, *hs1;
    cudaGetSymbolAddress((void**)&x0,  g_x0);
    cudaGetSymbolAddress((void**)&xgp, g_xg);
    cudaGetSymbolAddress((void**)&hs1, g_hs1);

    const int per_smem = (40 * WST1 + 256 * 9 + 256 + 64) * (int)sizeof(float); // 176256
    cudaFuncSetAttribute(lstm_persist_kernel,
                         cudaFuncAttributeMaxDynamicSharedMemorySize, per_smem);
    cudaFuncSetAttribute(gemm_tf32_kernel,
                         cudaFuncAttributeMaxDynamicSharedMemorySize, GEMM_SMEM);

    // 1) gather embeddings
    gather_kernel<<<M_TOT, EMB / 4>>>(ids, emb);

    // 2) xg = x0 @ W_ih0^T + b_ih0 + b_hh0     [4096 x 2048], K=256
    gemm_tf32_kernel<<<dim3(G4H / 128, M_TOT / 128), 256, GEMM_SMEM>>>(
        x0, W_ih0, b_ih0, b_hh0, xgp, M_TOT, G4H, EMB);

    // 3) reset barrier + h buffers
    reset_kernel<<<(HID * BATCH + 255) / 256, 256>>>();

    // 4) both LSTM layers in ONE persistent wavefront launch
    lstm_persist_kernel<<<NCTA_TOT, 256, per_smem>>>(
        W_hh0, xgp, W_hh1, W_ih1, b_ih1, b_hh1, hs1);

    // 5) logits = hs1 @ W_fc^T + b_fc          [4096 x 32000], K=512
    gemm_tf32_kernel<<<dim3(VOCAB / 128, M_TOT / 128), 256, GEMM_SMEM>>>(
        hs1, W_fc, b_fc, nullptr, out, M_TOT, VOCAB, HID);
}

// round 13
// speedup vs baseline: 1.2805x; 1.2805x over previous
#include <cuda_runtime.h>
#include <cstdint>
#include <math.h>

// Problem dims
#define T_SEQ 512
#define BATCH 8
#define HID   512
#define EMB   256
#define VOCAB 32000
#define M_TOT (BATCH*T_SEQ)   // 4096
#define G4H   (4*HID)         // 2048

typedef unsigned long long u64;

// ---------------- scratch (device globals; no allocation allowed) -----------
__device__ float    g_x0 [M_TOT*EMB];      // gathered embeddings
__device__ float    g_xg [M_TOT*G4H];      // layer0 input-gate contributions
__device__ float    g_hs1[M_TOT*HID];      // layer1 outputs (FC input)
__device__ float    g_h0 [2][HID*BATCH];   // double-buffered h0, layout [n][b]
__device__ float    g_h1 [2][HID*BATCH];   // double-buffered h1
__device__ unsigned g_bar;                 // monotonic wavefront barrier
__device__ unsigned g_abort;               // safety abort flag

// ---------------- embedding gather ------------------------------------------
__global__ void gather_kernel(const int* __restrict__ ids,
                              const float* __restrict__ emb) {
    int m  = blockIdx.x;
    int id = ids[m];
    const float4* s = (const float4*)(emb + (size_t)id * EMB);
    float4*       d = (float4*)(g_x0 + (size_t)m * EMB);
    d[threadIdx.x] = s[threadIdx.x];
}

// ---------------- barrier / h-buffer reset (before the recurrence) ----------
__global__ void reset_kernel() {
    int i = blockIdx.x * blockDim.x + threadIdx.x;
    if (i == 0) { g_bar = 0u; g_abort = 0u; }
    if (i < HID * BATCH) {
        g_h0[0][i] = 0.f; g_h0[1][i] = 0.f;
        g_h1[0][i] = 0.f; g_h1[1][i] = 0.f;
    }
}

// ---------------- tf32 mma GEMM (R11 version: static smem, known-good) ------
__device__ __forceinline__ float f2tf32(float x) {
    float r;
    asm("cvt.rna.tf32.f32 %0, %1;" : "=f"(r) : "f"(x));
    return r;
}

__global__ void __launch_bounds__(256)
gemm_tf32_kernel(const float* __restrict__ A, const float* __restrict__ B,
                 const float* __restrict__ bias1, const float* __restrict__ bias2,
                 float* __restrict__ C, int M, int N, int K)
{
    __shared__ float As[128][36];
    __shared__ float Bs[128][36];

    int tid  = threadIdx.x;
    int warp = tid >> 5, lane = tid & 31;
    int wm   = warp >> 2, wn = warp & 3;
    int grp  = lane >> 2, tig = lane & 3;

    int mBase = blockIdx.y << 7;
    int nBase = blockIdx.x << 7;

    float acc[4][4][4];
    #pragma unroll
    for (int a = 0; a < 4; a++)
        #pragma unroll
        for (int b = 0; b < 4; b++)
            #pragma unroll
            for (int c = 0; c < 4; c++) acc[a][b][c] = 0.f;

    for (int k0 = 0; k0 < K; k0 += 32) {
        #pragma unroll
        for (int i = 0; i < 4; i++) {
            int f  = tid + (i << 8);
            int m  = f >> 3;
            int k4 = (f & 7) << 2;
            float4 va = *(const float4*)(A + (size_t)(mBase + m) * K + k0 + k4);
            *(float4*)&As[m][k4] = make_float4(f2tf32(va.x), f2tf32(va.y),
                                               f2tf32(va.z), f2tf32(va.w));
            float4 vb = *(const float4*)(B + (size_t)(nBase + m) * K + k0 + k4);
            *(float4*)&Bs[m][k4] = make_float4(f2tf32(vb.x), f2tf32(vb.y),
                                               f2tf32(vb.z), f2tf32(vb.w));
        }
        __syncthreads();

        #pragma unroll
        for (int kk = 0; kk < 32; kk += 8) {
            uint32_t af[4][4], bf[4][2];
            #pragma unroll
            for (int mi = 0; mi < 4; mi++) {
                int r = (wm << 6) + (mi << 4);
                af[mi][0] = __float_as_uint(As[r + grp    ][kk + tig    ]);
                af[mi][1] = __float_as_uint(As[r + grp + 8][kk + tig    ]);
                af[mi][2] = __float_as_uint(As[r + grp    ][kk + tig + 4]);
                af[mi][3] = __float_as_uint(As[r + grp + 8][kk + tig + 4]);
            }
            #pragma unroll
            for (int ni = 0; ni < 4; ni++) {
                int cN = (wn << 5) + (ni << 3);
                bf[ni][0] = __float_as_uint(Bs[cN + grp][kk + tig    ]);
                bf[ni][1] = __float_as_uint(Bs[cN + grp][kk + tig + 4]);
            }
            #pragma unroll
            for (int mi = 0; mi < 4; mi++)
                #pragma unroll
                for (int ni = 0; ni < 4; ni++)
                    asm volatile(
                        "mma.sync.aligned.m16n8k8.row.col.f32.tf32.tf32.f32 "
                        "{%0,%1,%2,%3}, {%4,%5,%6,%7}, {%8,%9}, {%0,%1,%2,%3};"
                        : "+f"(acc[mi][ni][0]), "+f"(acc[mi][ni][1]),
                          "+f"(acc[mi][ni][2]), "+f"(acc[mi][ni][3])
                        : "r"(af[mi][0]), "r"(af[mi][1]),
                          "r"(af[mi][2]), "r"(af[mi][3]),
                          "r"(bf[ni][0]), "r"(bf[ni][1]));
        }
        __syncthreads();
    }

    #pragma unroll
    for (int mi = 0; mi < 4; mi++) {
        int mrow = mBase + (wm << 6) + (mi << 4) + grp;
        #pragma unroll
        for (int ni = 0; ni < 4; ni++) {
            int nc = nBase + (wn << 5) + (ni << 3) + (tig << 1);
            float b0 = bias1[nc], b1 = bias1[nc + 1];
            if (bias2) { b0 += bias2[nc]; b1 += bias2[nc + 1]; }
            float2 v0 = make_float2(acc[mi][ni][0] + b0, acc[mi][ni][1] + b1);
            float2 v1 = make_float2(acc[mi][ni][2] + b0, acc[mi][ni][3] + b1);
            *(float2*)(C + (size_t)mrow       * N + nc) = v0;
            *(float2*)(C + (size_t)(mrow + 8) * N + nc) = v1;
        }
    }
}

// ---------------- fast activations (MUFU ex2/rcp; rel err ~1e-6) ------------
__device__ __forceinline__ float fast_sig(float x) {
    float e, r;
    asm("ex2.approx.ftz.f32 %0, %1;" : "=f"(e) : "f"(-1.4426950408889634f * x));
    asm("rcp.approx.ftz.f32 %0, %1;" : "=f"(r) : "f"(1.f + e));
    return r;
}
__device__ __forceinline__ float fast_tanh(float x) {
    float e, r;
    asm("ex2.approx.ftz.f32 %0, %1;" : "=f"(e) : "f"(-2.8853900817779268f * x));
    asm("rcp.approx.ftz.f32 %0, %1;" : "=f"(r) : "f"(1.f + e));
    return 2.f * r - 1.f;
}

// ---------------- persistent wavefront LSTM ---------------------------------
// ONE launch, 128 CTAs, all co-resident. CTAs 0..63: layer0 (8 units each);
// 64..127: layer1. Wavefront l: layer0 computes t=l (l<512), layer1 t=l-1
// (l>=1). W in SMEM for the whole sequence. h via double-buffered globals +
// release/acquire monotonic barrier (no membars, no nanosleep quantization).
#define NCTA_TOT 128
#define WST0 516
#define WST1 1036

#define FMA2(a, x, y) \
    asm("fma.rn.f32x2 %0, %1, %2, %0;" : "+l"(a) : "l"(x), "l"(y))

__global__ void __launch_bounds__(256)
lstm_persist_kernel(const float* __restrict__ Whh0, const float* __restrict__ xg,
                    const float* __restrict__ Whh1, const float* __restrict__ Wih1,
                    const float* __restrict__ bi1,  const float* __restrict__ bh1,
                    float* __restrict__ hs1)
{
    extern __shared__ float sm[];
    __shared__ int s_ab[8];
    int tid  = threadIdx.x;
    bool isL1 = blockIdx.x >= 64;
    int base = (isL1 ? blockIdx.x - 64 : blockIdx.x) << 3;

    const int WST = isL1 ? WST1 : WST0;
    float* Ws = sm;                    // 32 rows x WST
    float* Hb = sm + 32 * WST;         //  8 x WST  (h inputs, [b][k])
    float* Pt = Hb + 8 * WST;          // 256 x 9 k-partials
    float* Cs = Pt + 256 * 9;          // 64 cell states

    // ---- one-time staging ----
    if (!isL1) {
        #pragma unroll 4
        for (int i = tid; i < 4096; i += 256) {
            int r = i >> 7, c4 = (i & 127) << 2;
            int g = r >> 3, u = r & 7;
            *(float4*)(Ws + r * WST0 + c4) =
                *(const float4*)(Whh0 + (size_t)((g << 9) + base + u) * HID + c4);
        }
    } else {
        #pragma unroll 4
        for (int i = tid; i < 8192; i += 256) {
            int r = i >> 8, c4 = (i & 255) << 2;
            int g = r >> 3, u = r & 7;
            const float* src = (c4 < 512) ? Whh1 : Wih1;
            int col = (c4 < 512) ? c4 : c4 - 512;
            *(float4*)(Ws + r * WST1 + c4) =
                *(const float4*)(src + (size_t)((g << 9) + base + u) * HID + col);
        }
    }
    for (int i = tid; i < 8 * WST; i += 256) Hb[i] = 0.f;
    if (tid < 64) Cs[tid] = 0.f;
    if (tid < 8)  s_ab[tid] = 0;

    // act-thread constants (tid < 64): u = tid>>3, b = tid&7
    int au = tid >> 3, ab_ = tid & 7;
    float bias_g[4] = {0.f, 0.f, 0.f, 0.f};
    if (isL1 && tid < 64) {
        #pragma unroll
        for (int g = 0; g < 4; g++) {
            int row = (g << 9) + base + au;
            bias_g[g] = __ldg(bi1 + row) + __ldg(bh1 + row);
        }
    }
    __syncthreads();

    // dot-phase mapping: lane = row, warp = k slice
    int w    = tid >> 5, lane = tid & 31;
    int ncw  = isL1 ? 32 : 16;
    int cb   = w * ncw;
    const ulonglong2* wp = (const ulonglong2*)(Ws + lane * WST) + cb;

    unsigned* barp = &g_bar;
    volatile unsigned* abtp = (volatile unsigned*)&g_abort;

    for (int l = 0; l <= T_SEQ; l++) {
        int wpar   = l & 1;
        bool active = isL1 ? (l >= 1) : (l < T_SEQ);
        int t = isL1 ? (l - 1) : l;

        // L0 act threads prefetch xg early (consumed after sync1)
        float xv0 = 0.f, xv1 = 0.f, xv2 = 0.f, xv3 = 0.f;
        if (!isL1 && active && tid < 64) {
            const float* xr = xg + (size_t)((ab_ << 9) + t) * G4H + base + au;
            xv0 = __ldg(xr);
            xv1 = __ldg(xr + 512);
            xv2 = __ldg(xr + 1024);
            xv3 = __ldg(xr + 1536);
        }

        if (active) {
            u64 acc[8];
            #pragma unroll
            for (int b = 0; b < 8; b++) acc[b] = 0ull;

            const ulonglong2* h0p = (const ulonglong2*)(Hb + 0 * WST) + cb;
            const ulonglong2* h1p = (const ulonglong2*)(Hb + 1 * WST) + cb;
            const ulonglong2* h2p = (const ulonglong2*)(Hb + 2 * WST) + cb;
            const ulonglong2* h3p = (const ulonglong2*)(Hb + 3 * WST) + cb;
            const ulonglong2* h4p = (const ulonglong2*)(Hb + 4 * WST) + cb;
            const ulonglong2* h5p = (const ulonglong2*)(Hb + 5 * WST) + cb;
            const ulonglong2* h6p = (const ulonglong2*)(Hb + 6 * WST) + cb;
            const ulonglong2* h7p = (const ulonglong2*)(Hb + 7 * WST) + cb;

            #pragma unroll 4
            for (int c = 0; c < ncw; c++) {
                ulonglong2 wv = wp[c];
                ulonglong2 h;
                h = h0p[c]; FMA2(acc[0], wv.x, h.x); FMA2(acc[0], wv.y, h.y);
                h = h1p[c]; FMA2(acc[1], wv.x, h.x); FMA2(acc[1], wv.y, h.y);
                h = h2p[c]; FMA2(acc[2], wv.x, h.x); FMA2(acc[2], wv.y, h.y);
                h = h3p[c]; FMA2(acc[3], wv.x, h.x); FMA2(acc[3], wv.y, h.y);
                h = h4p[c]; FMA2(acc[4], wv.x, h.x); FMA2(acc[4], wv.y, h.y);
                h = h5p[c]; FMA2(acc[5], wv.x, h.x); FMA2(acc[5], wv.y, h.y);
                h = h6p[c]; FMA2(acc[6], wv.x, h.x); FMA2(acc[6], wv.y, h.y);
                h = h7p[c]; FMA2(acc[7], wv.x, h.x); FMA2(acc[7], wv.y, h.y);
            }
            #pragma unroll
            for (int b = 0; b < 8; b++) {
                float lo, hi;
                asm("mov.b64 {%0,%1}, %2;" : "=f"(lo), "=f"(hi) : "l"(acc[b]));
                Pt[((lane << 3) + b) * 9 + w] = lo + hi;
            }
        }
        __syncthreads();                 // sync1: Pt complete

        if (active && tid < 64) {        // fused reduce + activations + publish
            float gs[4];
            #pragma unroll
            for (int g = 0; g < 4; g++) {
                int slot = (((g << 3) + au) << 3) + ab_;
                float s = 0.f;
                #pragma unroll
                for (int k = 0; k < 8; k++) s += Pt[slot * 9 + k];
                gs[g] = s;
            }
            if (!isL1) { gs[0] += xv0; gs[1] += xv1; gs[2] += xv2; gs[3] += xv3; }
            else       { gs[0] += bias_g[0]; gs[1] += bias_g[1];
                         gs[2] += bias_g[2]; gs[3] += bias_g[3]; }

            float i_ = fast_sig(gs[0]);
            float f_ = fast_sig(gs[1]);
            float gg = fast_tanh(gs[2]);
            float o_ = fast_sig(gs[3]);
            float c  = f_ * Cs[tid] + i_ * gg;
            Cs[tid]  = c;
            float h  = o_ * fast_tanh(c);
            if (!isL1) {
                g_h0[wpar][(base << 3) + tid] = h;       // contiguous 256B
            } else {
                g_h1[wpar][(base << 3) + tid] = h;
                hs1[(size_t)((ab_ << 9) + t) * HID + base + au] = h;
            }
        }
        __syncthreads();                 // sync2: h stores CTA-wide HB

        if (tid == 0)                    // release: orders all prior stores
            asm volatile("red.release.gpu.global.add.u32 [%0], 1;"
                         :: "l"(barp) : "memory");

        {                                // all-thread acquire poll, bounded
            unsigned target = (unsigned)NCTA_TOT * (unsigned)(l + 1);
            int saw = 0;
            unsigned it = 0;
            for (;;) {
                unsigned v;
                asm volatile("ld.acquire.gpu.global.u32 %0, [%1];"
                             : "=r"(v) : "l"(barp));
                if (v >= target) break;
                if ((++it & 63u) == 0u) {
                    if (*abtp) { saw = 1; break; }
                    if (it > (1u << 22)) { atomicExch(&g_abort, 1u); saw = 1; break; }
                    __nanosleep(32);
                }
            }
            if (lane == 0) s_ab[w] = saw;
        }

        // refresh Hb (per-warp safe: all Hb reads finished before sync1)
        if (!isL1) {
            const float4* s4 = (const float4*)g_h0[wpar];
            #pragma unroll
            for (int i = tid; i < 1024; i += 256) {
                float4 v = __ldcg(s4 + i);
                int k = i >> 1, b0 = (i & 1) << 2;
                Hb[(b0    ) * WST0 + k] = v.x;
                Hb[(b0 + 1) * WST0 + k] = v.y;
                Hb[(b0 + 2) * WST0 + k] = v.z;
                Hb[(b0 + 3) * WST0 + k] = v.w;
            }
        } else {
            const float4* s14 = (const float4*)g_h1[wpar];
            const float4* s04 = (const float4*)g_h0[wpar];
            #pragma unroll
            for (int i = tid; i < 2048; i += 256) {
                int half = i >> 10;                 // 0: h1, 1: h0 (cols +512)
                int j = i & 1023;
                float4 v = __ldcg((half ? s04 : s14) + j);
                int k = (j >> 1) + (half << 9), b0 = (j & 1) << 2;
                Hb[(b0    ) * WST1 + k] = v.x;
                Hb[(b0 + 1) * WST1 + k] = v.y;
                Hb[(b0 + 2) * WST1 + k] = v.z;
                Hb[(b0 + 3) * WST1 + k] = v.w;
            }
        }
        __syncthreads();                 // sync3: Hb ready; s_ab stable

        int ab = s_ab[0] | s_ab[1] | s_ab[2] | s_ab[3]
               | s_ab[4] | s_ab[5] | s_ab[6] | s_ab[7];
        if (ab) return;                  // uniform, hang-proof exit
    }
}

// ---------------- launch -----------------------------------------------------
extern "C" void kernel_launch(void* const* d_in, const int* in_sizes, int n_in,
                              void* d_out, int out_size)
{
    (void)in_sizes; (void)n_in; (void)out_size;
    const int*   ids   = (const int*)d_in[0];
    const float* emb   = (const float*)d_in[1];
    const float* W_ih0 = (const float*)d_in[2];
    const float* W_hh0 = (const float*)d_in[3];
    const float* b_ih0 = (const float*)d_in[4];
    const float* b_hh0 = (const float*)d_in[5];
    const float* W_ih1 = (const float*)d_in[6];
    const float* W_hh1 = (const float*)d_in[7];
    const float* b_ih1 = (const float*)d_in[8];
    const float* b_hh1 = (const float*)d_in[9];
    const float* W_fc  = (const float*)d_in[10];
    const float* b_fc  = (const float*)d_in[11];
    float* out = (float*)d_out;

    float *x0, *xgp, *hs1;
    cudaGetSymbolAddress((void**)&x0,  g_x0);
    cudaGetSymbolAddress((void**)&xgp, g_xg);
    cudaGetSymbolAddress((void**)&hs1, g_hs1);

    // dynamic smem (L1 branch): 40*WST1 + 256*9 + 64 floats
    const int per_smem = (40 * WST1 + 256 * 9 + 64) * (int)sizeof(float); // 175232
    cudaFuncSetAttribute(lstm_persist_kernel,
                         cudaFuncAttributeMaxDynamicSharedMemorySize, per_smem);

    // 1) gather embeddings
    gather_kernel<<<M_TOT, EMB / 4>>>(ids, emb);

    // 2) xg = x0 @ W_ih0^T + b_ih0 + b_hh0     [4096 x 2048], K=256
    gemm_tf32_kernel<<<dim3(G4H / 128, M_TOT / 128), 256>>>(
        x0, W_ih0, b_ih0, b_hh0, xgp, M_TOT, G4H, EMB);

    // 3) reset barrier + h buffers
    reset_kernel<<<(HID * BATCH + 255) / 256, 256>>>();

    // 4) both LSTM layers in ONE persistent wavefront launch
    lstm_persist_kernel<<<NCTA_TOT, 256, per_smem>>>(
        W_hh0, xgp, W_hh1, W_ih1, b_ih1, b_hh1, hs1);

    // 5) logits = hs1 @ W_fc^T + b_fc          [4096 x 32000], K=512
    gemm_tf32_kernel<<<dim3(VOCAB / 128, M_TOT / 128), 256>>>(
        hs1, W_fc, b_fc, nullptr, out, M_TOT, VOCAB, HID);
}

// round 14
// speedup vs baseline: 1.3105x; 1.0234x over previous
#include <cuda_runtime.h>
#include <cstdint>
#include <math.h>

// Problem dims
#define T_SEQ 512
#define BATCH 8
#define HID   512
#define EMB   256
#define VOCAB 32000
#define M_TOT (BATCH*T_SEQ)   // 4096
#define G4H   (4*HID)         // 2048

typedef unsigned long long u64;

// ---------------- scratch (device globals; no allocation allowed) -----------
__device__ float    g_x0 [M_TOT*EMB];      // gathered embeddings
__device__ float    g_xg [M_TOT*G4H];      // layer0 input-gate contributions
__device__ float    g_hs1[M_TOT*HID];      // layer1 outputs (FC input)
__device__ float    g_h0 [4][HID*BATCH];   // RING-buffered h0 (depth 4), [n][b]
__device__ float    g_h1 [2][HID*BATCH];   // double-buffered h1
__device__ unsigned g_bar0;                // layer0 monotonic barrier
__device__ unsigned g_bar1;                // layer1 monotonic barrier
__device__ unsigned g_abort;               // safety abort flag

// ---------------- embedding gather ------------------------------------------
__global__ void gather_kernel(const int* __restrict__ ids,
                              const float* __restrict__ emb) {
    int m  = blockIdx.x;
    int id = ids[m];
    const float4* s = (const float4*)(emb + (size_t)id * EMB);
    float4*       d = (float4*)(g_x0 + (size_t)m * EMB);
    d[threadIdx.x] = s[threadIdx.x];
}

// ---------------- barrier reset (before the recurrence) ---------------------
__global__ void reset_kernel() {
    if (blockIdx.x == 0 && threadIdx.x == 0) {
        g_bar0 = 0u; g_bar1 = 0u; g_abort = 0u;
    }
}

// ---------------- tf32 mma GEMM (static smem, known-good) -------------------
__device__ __forceinline__ float f2tf32(float x) {
    float r;
    asm("cvt.rna.tf32.f32 %0, %1;" : "=f"(r) : "f"(x));
    return r;
}

__global__ void __launch_bounds__(256)
gemm_tf32_kernel(const float* __restrict__ A, const float* __restrict__ B,
                 const float* __restrict__ bias1, const float* __restrict__ bias2,
                 float* __restrict__ C, int M, int N, int K)
{
    __shared__ float As[128][36];
    __shared__ float Bs[128][36];

    int tid  = threadIdx.x;
    int warp = tid >> 5, lane = tid & 31;
    int wm   = warp >> 2, wn = warp & 3;
    int grp  = lane >> 2, tig = lane & 3;

    int mBase = blockIdx.y << 7;
    int nBase = blockIdx.x << 7;

    float acc[4][4][4];
    #pragma unroll
    for (int a = 0; a < 4; a++)
        #pragma unroll
        for (int b = 0; b < 4; b++)
            #pragma unroll
            for (int c = 0; c < 4; c++) acc[a][b][c] = 0.f;

    for (int k0 = 0; k0 < K; k0 += 32) {
        #pragma unroll
        for (int i = 0; i < 4; i++) {
            int f  = tid + (i << 8);
            int m  = f >> 3;
            int k4 = (f & 7) << 2;
            float4 va = *(const float4*)(A + (size_t)(mBase + m) * K + k0 + k4);
            *(float4*)&As[m][k4] = make_float4(f2tf32(va.x), f2tf32(va.y),
                                               f2tf32(va.z), f2tf32(va.w));
            float4 vb = *(const float4*)(B + (size_t)(nBase + m) * K + k0 + k4);
            *(float4*)&Bs[m][k4] = make_float4(f2tf32(vb.x), f2tf32(vb.y),
                                               f2tf32(vb.z), f2tf32(vb.w));
        }
        __syncthreads();

        #pragma unroll
        for (int kk = 0; kk < 32; kk += 8) {
            uint32_t af[4][4], bf[4][2];
            #pragma unroll
            for (int mi = 0; mi < 4; mi++) {
                int r = (wm << 6) + (mi << 4);
                af[mi][0] = __float_as_uint(As[r + grp    ][kk + tig    ]);
                af[mi][1] = __float_as_uint(As[r + grp + 8][kk + tig    ]);
                af[mi][2] = __float_as_uint(As[r + grp    ][kk + tig + 4]);
                af[mi][3] = __float_as_uint(As[r + grp + 8][kk + tig + 4]);
            }
            #pragma unroll
            for (int ni = 0; ni < 4; ni++) {
                int cN = (wn << 5) + (ni << 3);
                bf[ni][0] = __float_as_uint(Bs[cN + grp][kk + tig    ]);
                bf[ni][1] = __float_as_uint(Bs[cN + grp][kk + tig + 4]);
            }
            #pragma unroll
            for (int mi = 0; mi < 4; mi++)
                #pragma unroll
                for (int ni = 0; ni < 4; ni++)
                    asm volatile(
                        "mma.sync.aligned.m16n8k8.row.col.f32.tf32.tf32.f32 "
                        "{%0,%1,%2,%3}, {%4,%5,%6,%7}, {%8,%9}, {%0,%1,%2,%3};"
                        : "+f"(acc[mi][ni][0]), "+f"(acc[mi][ni][1]),
                          "+f"(acc[mi][ni][2]), "+f"(acc[mi][ni][3])
                        : "r"(af[mi][0]), "r"(af[mi][1]),
                          "r"(af[mi][2]), "r"(af[mi][3]),
                          "r"(bf[ni][0]), "r"(bf[ni][1]));
        }
        __syncthreads();
    }

    #pragma unroll
    for (int mi = 0; mi < 4; mi++) {
        int mrow = mBase + (wm << 6) + (mi << 4) + grp;
        #pragma unroll
        for (int ni = 0; ni < 4; ni++) {
            int nc = nBase + (wn << 5) + (ni << 3) + (tig << 1);
            float b0 = bias1[nc], b1 = bias1[nc + 1];
            if (bias2) { b0 += bias2[nc]; b1 += bias2[nc + 1]; }
            float2 v0 = make_float2(acc[mi][ni][0] + b0, acc[mi][ni][1] + b1);
            float2 v1 = make_float2(acc[mi][ni][2] + b0, acc[mi][ni][3] + b1);
            *(float2*)(C + (size_t)mrow       * N + nc) = v0;
            *(float2*)(C + (size_t)(mrow + 8) * N + nc) = v1;
        }
    }
}

// ---------------- fast activations (MUFU ex2/rcp; rel err ~1e-6) ------------
__device__ __forceinline__ float fast_sig(float x) {
    float e, r;
    asm("ex2.approx.ftz.f32 %0, %1;" : "=f"(e) : "f"(-1.4426950408889634f * x));
    asm("rcp.approx.ftz.f32 %0, %1;" : "=f"(r) : "f"(1.f + e));
    return r;
}
__device__ __forceinline__ float fast_tanh(float x) {
    float e, r;
    asm("ex2.approx.ftz.f32 %0, %1;" : "=f"(e) : "f"(-2.8853900817779268f * x));
    asm("rcp.approx.ftz.f32 %0, %1;" : "=f"(r) : "f"(1.f + e));
    return 2.f * r - 1.f;
}

// ---------------- bounded acquire-poll (hang-proof) --------------------------
__device__ __forceinline__ int poll_ge(unsigned* p, unsigned target) {
    volatile unsigned* abt = (volatile unsigned*)&g_abort;
    unsigned it = 0;
    for (;;) {
        unsigned v;
        asm volatile("ld.acquire.gpu.global.u32 %0, [%1];" : "=r"(v) : "l"(p));
        if (v >= target) return 0;
        if ((++it & 63u) == 0u) {
            if (*abt) return 1;
            if (it > (1u << 22)) { atomicExch(&g_abort, 1u); return 1; }
            __nanosleep(32);
        }
    }
}

// ---------------- persistent DECOUPLED-layer LSTM ----------------------------
// 128 CTAs, all co-resident. CTAs 0..63: layer0; 64..127: layer1. Each layer
// runs its own t=0..511 loop with its OWN 64-CTA barrier. h0 is a depth-4
// ring: L0 may run up to 3 steps ahead of L1 (write guard on bar1); L1 waits
// on bar0 only for h0_t availability (normally pre-satisfied).
//   dependency graph: L0_t <- L1_{t-4} <- L0_{t-4}   (acyclic, hang-free)
#define NCTA_L 64
#define WST0 516
#define WST1 1036

#define FMA2(a, x, y) \
    asm("fma.rn.f32x2 %0, %1, %2, %0;" : "+l"(a) : "l"(x), "l"(y))

__global__ void __launch_bounds__(256)
lstm_persist_kernel(const float* __restrict__ Whh0, const float* __restrict__ xg,
                    const float* __restrict__ Whh1, const float* __restrict__ Wih1,
                    const float* __restrict__ bi1,  const float* __restrict__ bh1,
                    float* __restrict__ hs1)
{
    extern __shared__ float sm[];
    __shared__ int s_ab[8];
    int tid  = threadIdx.x;
    bool isL1 = blockIdx.x >= 64;
    int base = (isL1 ? blockIdx.x - 64 : blockIdx.x) << 3;

    const int WST = isL1 ? WST1 : WST0;
    float* Ws = sm;                    // 32 rows x WST
    float* Hb = sm + 32 * WST;         //  8 x WST  (h inputs, [b][k])
    float* Pt = Hb + 8 * WST;          // 256 x 9 k-partials
    float* Cs = Pt + 256 * 9;          // 64 cell states

    // ---- one-time staging ----
    if (!isL1) {
        #pragma unroll 4
        for (int i = tid; i < 4096; i += 256) {
            int r = i >> 7, c4 = (i & 127) << 2;
            int g = r >> 3, u = r & 7;
            *(float4*)(Ws + r * WST0 + c4) =
                *(const float4*)(Whh0 + (size_t)((g << 9) + base + u) * HID + c4);
        }
    } else {
        #pragma unroll 4
        for (int i = tid; i < 8192; i += 256) {
            int r = i >> 8, c4 = (i & 255) << 2;
            int g = r >> 3, u = r & 7;
            const float* src = (c4 < 512) ? Whh1 : Wih1;
            int col = (c4 < 512) ? c4 : c4 - 512;
            *(float4*)(Ws + r * WST1 + c4) =
                *(const float4*)(src + (size_t)((g << 9) + base + u) * HID + col);
        }
    }
    for (int i = tid; i < 8 * WST; i += 256) Hb[i] = 0.f;
    if (tid < 64) Cs[tid] = 0.f;
    if (tid < 8)  s_ab[tid] = 0;

    int au = tid >> 3, ab_ = tid & 7;        // act-thread coords (tid < 64)
    float bias_g[4] = {0.f, 0.f, 0.f, 0.f};
    if (isL1 && tid < 64) {
        #pragma unroll
        for (int g = 0; g < 4; g++) {
            int row = (g << 9) + base + au;
            bias_g[g] = __ldg(bi1 + row) + __ldg(bh1 + row);
        }
    }
    __syncthreads();

    // dot-phase mapping: lane = row, warp = k slice
    int w    = tid >> 5, lane = tid & 31;
    int ncw  = isL1 ? 32 : 16;
    int cb   = w * ncw;
    const ulonglong2* wp = (const ulonglong2*)(Ws + lane * WST) + cb;

    if (!isL1) {
        // ================= LAYER 0 =================
        for (int t = 0; t < T_SEQ; t++) {
            // act threads prefetch xg (consumed after sync1)
            float xv0 = 0.f, xv1 = 0.f, xv2 = 0.f, xv3 = 0.f;
            if (tid < 64) {
                const float* xr = xg + (size_t)((ab_ << 9) + t) * G4H + base + au;
                xv0 = __ldg(xr);        xv1 = __ldg(xr + 512);
                xv2 = __ldg(xr + 1024); xv3 = __ldg(xr + 1536);
            }

            {   // dot over h0_{t-1} in Hb
                u64 acc[8];
                #pragma unroll
                for (int b = 0; b < 8; b++) acc[b] = 0ull;
                const ulonglong2* h0p = (const ulonglong2*)(Hb + 0 * WST0) + cb;
                const ulonglong2* h1p = (const ulonglong2*)(Hb + 1 * WST0) + cb;
                const ulonglong2* h2p = (const ulonglong2*)(Hb + 2 * WST0) + cb;
                const ulonglong2* h3p = (const ulonglong2*)(Hb + 3 * WST0) + cb;
                const ulonglong2* h4p = (const ulonglong2*)(Hb + 4 * WST0) + cb;
                const ulonglong2* h5p = (const ulonglong2*)(Hb + 5 * WST0) + cb;
                const ulonglong2* h6p = (const ulonglong2*)(Hb + 6 * WST0) + cb;
                const ulonglong2* h7p = (const ulonglong2*)(Hb + 7 * WST0) + cb;
                #pragma unroll 4
                for (int c = 0; c < 16; c++) {
                    ulonglong2 wv = wp[c];
                    ulonglong2 h;
                    h = h0p[c]; FMA2(acc[0], wv.x, h.x); FMA2(acc[0], wv.y, h.y);
                    h = h1p[c]; FMA2(acc[1], wv.x, h.x); FMA2(acc[1], wv.y, h.y);
                    h = h2p[c]; FMA2(acc[2], wv.x, h.x); FMA2(acc[2], wv.y, h.y);
                    h = h3p[c]; FMA2(acc[3], wv.x, h.x); FMA2(acc[3], wv.y, h.y);
                    h = h4p[c]; FMA2(acc[4], wv.x, h.x); FMA2(acc[4], wv.y, h.y);
                    h = h5p[c]; FMA2(acc[5], wv.x, h.x); FMA2(acc[5], wv.y, h.y);
                    h = h6p[c]; FMA2(acc[6], wv.x, h.x); FMA2(acc[6], wv.y, h.y);
                    h = h7p[c]; FMA2(acc[7], wv.x, h.x); FMA2(acc[7], wv.y, h.y);
                }
                #pragma unroll
                for (int b = 0; b < 8; b++) {
                    float lo, hi;
                    asm("mov.b64 {%0,%1}, %2;" : "=f"(lo), "=f"(hi) : "l"(acc[b]));
                    Pt[((lane << 3) + b) * 9 + w] = lo + hi;
                }
            }
            __syncthreads();                 // sync1: Pt complete

            // ring guard: slot t%4 must be consumed by L1 (step t-4 done)
            int ab = 0;
            if (t >= 4) ab = poll_ge(&g_bar1, (unsigned)NCTA_L * (unsigned)(t - 3));

            if (tid < 64) {                  // fused reduce + act + publish
                float gs[4];
                #pragma unroll
                for (int g = 0; g < 4; g++) {
                    int slot = (((g << 3) + au) << 3) + ab_;
                    float s = 0.f;
                    #pragma unroll
                    for (int k = 0; k < 8; k++) s += Pt[slot * 9 + k];
                    gs[g] = s;
                }
                gs[0] += xv0; gs[1] += xv1; gs[2] += xv2; gs[3] += xv3;
                float i_ = fast_sig(gs[0]);
                float f_ = fast_sig(gs[1]);
                float gg = fast_tanh(gs[2]);
                float o_ = fast_sig(gs[3]);
                float c  = f_ * Cs[tid] + i_ * gg;
                Cs[tid]  = c;
                g_h0[t & 3][(base << 3) + tid] = o_ * fast_tanh(c);
            }
            __syncthreads();                 // sync2: stores CTA-wide HB

            if (tid == 0)
                asm volatile("red.release.gpu.global.add.u32 [%0], 1;"
                             :: "l"(&g_bar0) : "memory");
            ab |= poll_ge(&g_bar0, (unsigned)NCTA_L * (unsigned)(t + 1));

            {   // refresh Hb with h0_t
                const float4* s4 = (const float4*)g_h0[t & 3];
                #pragma unroll
                for (int i = tid; i < 1024; i += 256) {
                    float4 v = __ldcg(s4 + i);
                    int k = i >> 1, b0 = (i & 1) << 2;
                    Hb[(b0    ) * WST0 + k] = v.x;
                    Hb[(b0 + 1) * WST0 + k] = v.y;
                    Hb[(b0 + 2) * WST0 + k] = v.z;
                    Hb[(b0 + 3) * WST0 + k] = v.w;
                }
            }
            if (lane == 0) s_ab[w] = ab;
            __syncthreads();                 // sync3: Hb ready; s_ab stable
            if (s_ab[0] | s_ab[1] | s_ab[2] | s_ab[3] |
                s_ab[4] | s_ab[5] | s_ab[6] | s_ab[7]) return;
        }
    } else {
        // ================= LAYER 1 =================
        for (int t = 0; t < T_SEQ; t++) {
            // wait for h0_t (normally pre-satisfied: L0 runs ahead)
            int ab = poll_ge(&g_bar0, (unsigned)NCTA_L * (unsigned)(t + 1));

            {   // copy h0_t into Hb cols [512,1024)
                const float4* s04 = (const float4*)g_h0[t & 3];
                #pragma unroll
                for (int i = tid; i < 1024; i += 256) {
                    float4 v = __ldcg(s04 + i);
                    int k = (i >> 1) + 512, b0 = (i & 1) << 2;
                    Hb[(b0    ) * WST1 + k] = v.x;
                    Hb[(b0 + 1) * WST1 + k] = v.y;
                    Hb[(b0 + 2) * WST1 + k] = v.z;
                    Hb[(b0 + 3) * WST1 + k] = v.w;
                }
            }
            __syncthreads();                 // sync0: Hb [h1_{t-1} | h0_t] ready

            {   // dot over concat [h1 | h0]
                u64 acc[8];
                #pragma unroll
                for (int b = 0; b < 8; b++) acc[b] = 0ull;
                const ulonglong2* h0p = (const ulonglong2*)(Hb + 0 * WST1) + cb;
                const ulonglong2* h1p = (const ulonglong2*)(Hb + 1 * WST1) + cb;
                const ulonglong2* h2p = (const ulonglong2*)(Hb + 2 * WST1) + cb;
                const ulonglong2* h3p = (const ulonglong2*)(Hb + 3 * WST1) + cb;
                const ulonglong2* h4p = (const ulonglong2*)(Hb + 4 * WST1) + cb;
                const ulonglong2* h5p = (const ulonglong2*)(Hb + 5 * WST1) + cb;
                const ulonglong2* h6p = (const ulonglong2*)(Hb + 6 * WST1) + cb;
                const ulonglong2* h7p = (const ulonglong2*)(Hb + 7 * WST1) + cb;
                #pragma unroll 4
                for (int c = 0; c < 32; c++) {
                    ulonglong2 wv = wp[c];
                    ulonglong2 h;
                    h = h0p[c]; FMA2(acc[0], wv.x, h.x); FMA2(acc[0], wv.y, h.y);
                    h = h1p[c]; FMA2(acc[1], wv.x, h.x); FMA2(acc[1], wv.y, h.y);
                    h = h2p[c]; FMA2(acc[2], wv.x, h.x); FMA2(acc[2], wv.y, h.y);
                    h = h3p[c]; FMA2(acc[3], wv.x, h.x); FMA2(acc[3], wv.y, h.y);
                    h = h4p[c]; FMA2(acc[4], wv.x, h.x); FMA2(acc[4], wv.y, h.y);
                    h = h5p[c]; FMA2(acc[5], wv.x, h.x); FMA2(acc[5], wv.y, h.y);
                    h = h6p[c]; FMA2(acc[6], wv.x, h.x); FMA2(acc[6], wv.y, h.y);
                    h = h7p[c]; FMA2(acc[7], wv.x, h.x); FMA2(acc[7], wv.y, h.y);
                }
                #pragma unroll
                for (int b = 0; b < 8; b++) {
                    float lo, hi;
                    asm("mov.b64 {%0,%1}, %2;" : "=f"(lo), "=f"(hi) : "l"(acc[b]));
                    Pt[((lane << 3) + b) * 9 + w] = lo + hi;
                }
            }
            __syncthreads();                 // sync1: Pt complete

            if (tid < 64) {                  // fused reduce + act + publish
                float gs[4];
                #pragma unroll
                for (int g = 0; g < 4; g++) {
                    int slot = (((g << 3) + au) << 3) + ab_;
                    float s = 0.f;
                    #pragma unroll
                    for (int k = 0; k < 8; k++) s += Pt[slot * 9 + k];
                    gs[g] = s + bias_g[g];
                }
                float i_ = fast_sig(gs[0]);
                float f_ = fast_sig(gs[1]);
                float gg = fast_tanh(gs[2]);
                float o_ = fast_sig(gs[3]);
                float c  = f_ * Cs[tid] + i_ * gg;
                Cs[tid]  = c;
                float h  = o_ * fast_tanh(c);
                g_h1[t & 1][(base << 3) + tid] = h;
                hs1[(size_t)((ab_ << 9) + t) * HID + base + au] = h;
            }
            __syncthreads();                 // sync2

            if (tid == 0)
                asm volatile("red.release.gpu.global.add.u32 [%0], 1;"
                             :: "l"(&g_bar1) : "memory");
            ab |= poll_ge(&g_bar1, (unsigned)NCTA_L * (unsigned)(t + 1));

            {   // refresh Hb cols [0,512) with h1_t
                const float4* s14 = (const float4*)g_h1[t & 1];
                #pragma unroll
                for (int i = tid; i < 1024; i += 256) {
                    float4 v = __ldcg(s14 + i);
                    int k = i >> 1, b0 = (i & 1) << 2;
                    Hb[(b0    ) * WST1 + k] = v.x;
                    Hb[(b0 + 1) * WST1 + k] = v.y;
                    Hb[(b0 + 2) * WST1 + k] = v.z;
                    Hb[(b0 + 3) * WST1 + k] = v.w;
                }
            }
            if (lane == 0) s_ab[w] = ab;
            __syncthreads();                 // sync3
            if (s_ab[0] | s_ab[1] | s_ab[2] | s_ab[3] |
                s_ab[4] | s_ab[5] | s_ab[6] | s_ab[7]) return;
        }
    }
}

// ---------------- launch -----------------------------------------------------
extern "C" void kernel_launch(void* const* d_in, const int* in_sizes, int n_in,
                              void* d_out, int out_size)
{
    (void)in_sizes; (void)n_in; (void)out_size;
    const int*   ids   = (const int*)d_in[0];
    const float* emb   = (const float*)d_in[1];
    const float* W_ih0 = (const float*)d_in[2];
    const float* W_hh0 = (const float*)d_in[3];
    const float* b_ih0 = (const float*)d_in[4];
    const float* b_hh0 = (const float*)d_in[5];
    const float* W_ih1 = (const float*)d_in[6];
    const float* W_hh1 = (const float*)d_in[7];
    const float* b_ih1 = (const float*)d_in[8];
    const float* b_hh1 = (const float*)d_in[9];
    const float* W_fc  = (const float*)d_in[10];
    const float* b_fc  = (const float*)d_in[11];
    float* out = (float*)d_out;

    float *x0, *xgp, *hs1;
    cudaGetSymbolAddress((void**)&x0,  g_x0);
    cudaGetSymbolAddress((void**)&xgp, g_xg);
    cudaGetSymbolAddress((void**)&hs1, g_hs1);

    // dynamic smem (L1 branch): 40*WST1 + 256*9 + 64 floats
    const int per_smem = (40 * WST1 + 256 * 9 + 64) * (int)sizeof(float); // 175232
    cudaFuncSetAttribute(lstm_persist_kernel,
                         cudaFuncAttributeMaxDynamicSharedMemorySize, per_smem);

    // 1) gather embeddings
    gather_kernel<<<M_TOT, EMB / 4>>>(ids, emb);

    // 2) xg = x0 @ W_ih0^T + b_ih0 + b_hh0     [4096 x 2048], K=256
    gemm_tf32_kernel<<<dim3(G4H / 128, M_TOT / 128), 256>>>(
        x0, W_ih0, b_ih0, b_hh0, xgp, M_TOT, G4H, EMB);

    // 3) reset barriers
    reset_kernel<<<1, 32>>>();

    // 4) both LSTM layers, decoupled, in ONE persistent launch
    lstm_persist_kernel<<<2 * NCTA_L, 256, per_smem>>>(
        W_hh0, xgp, W_hh1, W_ih1, b_ih1, b_hh1, hs1);

    // 5) logits = hs1 @ W_fc^T + b_fc          [4096 x 32000], K=512
    gemm_tf32_kernel<<<dim3(VOCAB / 128, M_TOT / 128), 256>>>(
        hs1, W_fc, b_fc, nullptr, out, M_TOT, VOCAB, HID);
}